// round 13
// baseline (speedup 1.0000x reference)
#include <cuda_runtime.h>
#include <cstdint>

#define CIN    32
#define COUT   64
#define KOFF   27
#define TILE   64       // pairs per block
#define APITCH 36       // raw A row pitch (floats)
#define DPITCH 72       // D bounce-buffer pitch (floats)

__device__ __forceinline__ uint32_t pack_bf16x2(float lo, float hi) {
    uint32_t r;
    asm("cvt.rn.bf16x2.f32 %0, %1, %2;" : "=r"(r) : "f"(hi), "f"(lo));
    return r;
}
__device__ __forceinline__ void split_bf16(float x, float y,
                                           uint32_t& h, uint32_t& l) {
    h = pack_bf16x2(x, y);
    float xh = __uint_as_float(h << 16);
    float yh = __uint_as_float(h & 0xFFFF0000u);
    l = pack_bf16x2(x - xh, y - yh);
}

#define MMA_BF16(D, A0, A1, A2, A3, B0, B1)                                   \
    asm volatile(                                                             \
        "mma.sync.aligned.m16n8k16.row.col.f32.bf16.bf16.f32 "                \
        "{%0,%1,%2,%3}, {%4,%5,%6,%7}, {%8,%9}, {%0,%1,%2,%3};"               \
        : "+f"(D[0]), "+f"(D[1]), "+f"(D[2]), "+f"(D[3])                      \
        : "r"(A0), "r"(A1), "r"(A2), "r"(A3), "r"(B0), "r"(B1))

// ---------------------------------------------------------------------------
// bf16 HMMA sparse conv, 3-term compensation. R12 math kept bit-identical;
// scatter rebuilt: fragments -> smem D_s (STS.128) -> dense RED pass where
// each red.v4 instr covers 2 pair-rows with 16 contiguous lanes each
// (2 cache lines per pair instead of 8).
// ---------------------------------------------------------------------------
__global__ __launch_bounds__(128, 4) void conv_tc_kernel(
    const float* __restrict__ feats,
    const float* __restrict__ W,
    const int*   __restrict__ in_idx,
    const int*   __restrict__ out_idx,
    float*       __restrict__ out,
    int M, int kBase)
{
    __shared__ __align__(16) float A_raw[TILE][APITCH];
    __shared__ __align__(16) float D_s[TILE][DPITCH];
    __shared__ int okv_s[TILE];

    const int tid  = threadIdx.x;
    const int wid  = tid >> 5;
    const int lane = tid & 31;
    const int gid  = lane >> 2;
    const int q    = lane & 3;
    const int k    = kBase + (int)blockIdx.y;
    const size_t kM = (size_t)k * M;

    // ---- B fragments (W[k] hi/lo, bf16) : identical to R12 (verified) ----
    uint32_t Bh[2][2][2], Bl[2][2][2];
    {
        const float* Wk = W + (size_t)k * (CIN * COUT);
        #pragma unroll
        for (int t = 0; t < 2; ++t) {
            const int n = (2 * wid + t) * 8 + gid;
            #pragma unroll
            for (int kb = 0; kb < 2; ++kb) {
                const int r0 = kb * 16 + 2 * q;
                float w0 = Wk[(r0    ) * COUT + n];
                float w1 = Wk[(r0 + 1) * COUT + n];
                float w2 = Wk[(r0 + 8) * COUT + n];
                float w3 = Wk[(r0 + 9) * COUT + n];
                split_bf16(w0, w1, Bh[t][kb][0], Bl[t][kb][0]);
                split_bf16(w2, w3, Bh[t][kb][1], Bl[t][kb][1]);
            }
        }
    }

    const int tileBase = (int)blockIdx.x * TILE;
    if (tileBase >= M) return;
    const int nv = (M - tileBase < TILE) ? (M - tileBase) : TILE;

    // ---- cooperative raw stage (identical to R12, verified) ----
    {
        int ikv = 0;
        const int rloc = 16 * wid + lane;
        if (lane < 16) {
            const bool v = (rloc < nv);
            ikv = v ? in_idx[kM + tileBase + rloc] : 0;
            okv_s[rloc] = v ? out_idx[kM + tileBase + rloc] : 0;
        }
        const int g   = lane >> 3;
        const int sec = lane & 7;
        const float4* fb = reinterpret_cast<const float4*>(feats);
        #pragma unroll
        for (int r = 0; r < 4; ++r) {
            const int rw = 4 * r + g;
            const int ik = __shfl_sync(0xffffffffu, ikv, rw);
            float4 v = fb[(size_t)ik * 8 + sec];
            *reinterpret_cast<float4*>(&A_raw[16 * wid + rw][4 * sec]) = v;
        }
    }
    __syncthreads();

    // ---- math per 16-pair M-block; results bounced into D_s ----
    #pragma unroll
    for (int mb = 0; mb < 4; ++mb) {
        if (mb * 16 >= nv) break;
        const int mbase = mb * 16;

        float d[2][4] = {{0.f, 0.f, 0.f, 0.f}, {0.f, 0.f, 0.f, 0.f}};

        #pragma unroll
        for (int kb = 0; kb < 2; ++kb) {
            const int c0 = kb * 16 + 2 * q;
            float2 p0 = *reinterpret_cast<const float2*>(&A_raw[mbase + gid    ][c0    ]);
            float2 p1 = *reinterpret_cast<const float2*>(&A_raw[mbase + gid + 8][c0    ]);
            float2 p2 = *reinterpret_cast<const float2*>(&A_raw[mbase + gid    ][c0 + 8]);
            float2 p3 = *reinterpret_cast<const float2*>(&A_raw[mbase + gid + 8][c0 + 8]);

            uint32_t ah0, ah1, ah2, ah3, al0, al1, al2, al3;
            split_bf16(p0.x, p0.y, ah0, al0);
            split_bf16(p1.x, p1.y, ah1, al1);
            split_bf16(p2.x, p2.y, ah2, al2);
            split_bf16(p3.x, p3.y, ah3, al3);

            #pragma unroll
            for (int t = 0; t < 2; ++t) {
                MMA_BF16(d[t], ah0, ah1, ah2, ah3, Bh[t][kb][0], Bh[t][kb][1]);
                MMA_BF16(d[t], ah0, ah1, ah2, ah3, Bl[t][kb][0], Bl[t][kb][1]);
                MMA_BF16(d[t], al0, al1, al2, al3, Bh[t][kb][0], Bh[t][kb][1]);
            }
        }

        // ---- v4 assembly (R12-verified shfl pairing), then STS to D_s ----
        #pragma unroll
        for (int t = 0; t < 2; ++t) {
            const int colBase = (2 * wid + t) * 8 + 2 * q;
            #pragma unroll
            for (int ro = 0; ro < 2; ++ro) {
                float x0 = ro ? d[t][2] : d[t][0];
                float x1 = ro ? d[t][3] : d[t][1];
                float y0 = __shfl_xor_sync(0xffffffffu, x0, 1);
                float y1 = __shfl_xor_sync(0xffffffffu, x1, 1);
                const int row = mbase + 8 * ro + gid;
                if ((lane & 1) == 0) {
                    *reinterpret_cast<float4*>(&D_s[row][colBase]) =
                        make_float4(x0, x1, y0, y1);
                }
            }
        }
    }
    __syncthreads();

    // ---- dense scatter: warp w handles pairs [16w, 16w+16); per instr
    //      2 pairs x 16 contiguous lanes -> 2 lines per pair. ----
    {
        const int pbase = wid * 16;
        const int sub   = lane >> 4;       // which of the 2 pairs
        const int j     = lane & 15;       // 16B chunk within the row
        #pragma unroll
        for (int it = 0; it < 8; ++it) {
            const int p = pbase + 2 * it + sub;
            if (p < nv) {
                float4 v = *reinterpret_cast<const float4*>(&D_s[p][4 * j]);
                float* dst = out + (size_t)okv_s[p] * COUT + 4 * j;
                asm volatile("red.global.v4.f32.add [%0], {%1, %2, %3, %4};"
                             :: "l"(dst), "f"(v.x), "f"(v.y), "f"(v.z), "f"(v.w)
                             : "memory");
            }
        }
    }
}

// ---------------------------------------------------------------------------
// In-place BatchNorm (inference) + ReLU epilogue, vectorized float4.
// ---------------------------------------------------------------------------
__global__ __launch_bounds__(256) void bn_relu_kernel(
    float* __restrict__ out,
    const float* __restrict__ gamma,
    const float* __restrict__ beta,
    const float* __restrict__ run_mean,
    const float* __restrict__ run_var,
    int n4)
{
    int i = blockIdx.x * blockDim.x + threadIdx.x;
    if (i >= n4) return;

    const int c0 = (i & 15) * 4;
    float4 v = reinterpret_cast<float4*>(out)[i];

    float s0 = gamma[c0 + 0] * rsqrtf(run_var[c0 + 0] + 1e-5f);
    float s1 = gamma[c0 + 1] * rsqrtf(run_var[c0 + 1] + 1e-5f);
    float s2 = gamma[c0 + 2] * rsqrtf(run_var[c0 + 2] + 1e-5f);
    float s3 = gamma[c0 + 3] * rsqrtf(run_var[c0 + 3] + 1e-5f);

    float t0 = beta[c0 + 0] - run_mean[c0 + 0] * s0;
    float t1 = beta[c0 + 1] - run_mean[c0 + 1] * s1;
    float t2 = beta[c0 + 2] - run_mean[c0 + 2] * s2;
    float t3 = beta[c0 + 3] - run_mean[c0 + 3] * s3;

    v.x = fmaxf(fmaf(v.x, s0, t0), 0.0f);
    v.y = fmaxf(fmaf(v.y, s1, t1), 0.0f);
    v.z = fmaxf(fmaf(v.z, s2, t2), 0.0f);
    v.w = fmaxf(fmaf(v.w, s3, t3), 0.0f);

    reinterpret_cast<float4*>(out)[i] = v;
}

// ---------------------------------------------------------------------------
// Launcher: memset(zero) -> 9x conv (3 offsets each; keeps ncu on conv)
//           -> BN+ReLU.
// ---------------------------------------------------------------------------
extern "C" void kernel_launch(void* const* d_in, const int* in_sizes, int n_in,
                              void* d_out, int out_size)
{
    const float* feats    = (const float*)d_in[0];
    const float* W        = (const float*)d_in[1];
    const float* gamma    = (const float*)d_in[2];
    const float* beta     = (const float*)d_in[3];
    const float* run_mean = (const float*)d_in[4];
    const float* run_var  = (const float*)d_in[5];
    const int*   in_idx   = (const int*)d_in[6];
    const int*   out_idx  = (const int*)d_in[7];
    float*       out      = (float*)d_out;

    const int KM = in_sizes[6];
    const int M  = KM / KOFF;

    cudaMemsetAsync(d_out, 0, (size_t)out_size * sizeof(float), 0);

    const int gx = (M + TILE - 1) / TILE;
    for (int kb = 0; kb < KOFF; kb += 3) {
        dim3 grid(gx, 3);
        conv_tc_kernel<<<grid, 128>>>(feats, W, in_idx, out_idx, out, M, kb);
    }

    const int n4 = out_size / 4;
    bn_relu_kernel<<<(n4 + 255) / 256, 256>>>(out, gamma, beta, run_mean, run_var, n4);
}